// round 14
// baseline (speedup 1.0000x reference)
#include <cuda_runtime.h>
#include <cuda_bf16.h>
#include <cstdint>

// Conv2d 3x3 s1 p1 NCHW fp32 — implicit GEMM on mma.sync bf16 (m16n8k16),
// 3-pass split precision: AhBh + AhBl + AlBh (al*bl dropped, ~2^-16 rel).
// GEMM: M=128 (C_out), N=802816 (spatial), K=576.
// R10/R13: B tiles double-buffered -> one __syncthreads per k-block; stsB flows
// immediately after compute per-warp (no rendezvous before the STS phase).
// (Resubmission of R10 — round 12 was an infra failure, change never measured.)

#define CI_   64
#define CO_   128
#define HDIM  224
#define WDIM  224
#define HW_   (HDIM*WDIM)          // 50176
#define KTOT  576
#define KBLK  64
#define NBLKS 9
#define BN    128
#define BPI   (HW_/BN)             // 392
#define NCTAS (16*BPI)             // 6272
#define XELEMS (16*CI_*HW_)        // 51380224
#define NTHR  512

#define SROW  144                  // padded row stride (bytes), 64 bf16 per row
#define TILE_B (128*SROW)          // 18432
// layout: A0h A0l A1h A1l B0h B0l B1h B1l
#define SMEM_TOTAL (8*TILE_B)      // 147456

__device__ __nv_bfloat16 g_wh[CO_*KTOT];
__device__ __nv_bfloat16 g_wl[CO_*KTOT];
__device__ uint32_t g_xp[XELEMS];   // packed: bf16_hi | bf16_lo << 16

static __device__ __forceinline__ uint32_t smem_u32(const void* p) {
    uint32_t a;
    asm("{ .reg .u64 t; cvta.to.shared.u64 t, %1; cvt.u32.u64 %0, t; }" : "=r"(a) : "l"(p));
    return a;
}
static __device__ __forceinline__ void ldsm_x4(uint32_t* r, uint32_t addr) {
    asm volatile("ldmatrix.sync.aligned.m8n8.x4.shared.b16 {%0,%1,%2,%3}, [%4];"
        : "=r"(r[0]), "=r"(r[1]), "=r"(r[2]), "=r"(r[3]) : "r"(addr));
}
static __device__ __forceinline__ void mma16816(float* c, const uint32_t* a, const uint32_t* b) {
    asm volatile(
        "mma.sync.aligned.m16n8k16.row.col.f32.bf16.bf16.f32 "
        "{%0,%1,%2,%3}, {%4,%5,%6,%7}, {%8,%9}, {%0,%1,%2,%3};"
        : "+f"(c[0]), "+f"(c[1]), "+f"(c[2]), "+f"(c[3])
        : "r"(a[0]), "r"(a[1]), "r"(a[2]), "r"(a[3]), "r"(b[0]), "r"(b[1]));
}
static __device__ __forceinline__ void cp16(uint32_t dst, const void* src) {
    asm volatile("cp.async.cg.shared.global [%0], [%1], 16;" :: "r"(dst), "l"(src));
}
#define CP_COMMIT() asm volatile("cp.async.commit_group;" ::: "memory")
#define CP_WAIT0()  asm volatile("cp.async.wait_group 0;" ::: "memory")

static __device__ __forceinline__ uint32_t pack_split(float v) {
    __nv_bfloat16 h = __float2bfloat16(v);
    __nv_bfloat16 l = __float2bfloat16(v - __bfloat162float(h));
    return (uint32_t)__bfloat16_as_ushort(h) | ((uint32_t)__bfloat16_as_ushort(l) << 16);
}

// ---------------- prologue kernels ----------------
__global__ void conv_prep_w(const float* __restrict__ w) {
    int i = blockIdx.x * 256 + threadIdx.x;
    if (i < CO_ * KTOT) {
        float v = w[i];
        __nv_bfloat16 h = __float2bfloat16(v);
        g_wh[i] = h;
        g_wl[i] = __float2bfloat16(v - __bfloat162float(h));
    }
}
__global__ void conv_prep_x(const float4* __restrict__ x4) {
    int i = blockIdx.x * 256 + threadIdx.x;
    float4 v = x4[i];
    uint4 p;
    p.x = pack_split(v.x); p.y = pack_split(v.y);
    p.z = pack_split(v.z); p.w = pack_split(v.w);
    reinterpret_cast<uint4*>(g_xp)[i] = p;
}

// ---------------- main kernel ----------------
__global__ void __launch_bounds__(NTHR)
conv_mma_kernel(const float* __restrict__ bias,
                float* __restrict__ out) {
    extern __shared__ char smem[];
    const uint32_t sBase = smem_u32(smem);

    const int tid = threadIdx.x;
    const int wid = tid >> 5;
    const int lid = tid & 31;
    const int warp_m = wid & 3;       // 4 warps over M, 32 rows each
    const int warp_n = wid >> 2;      // 4 warps over N, 32 cols each

    const int bi    = blockIdx.x;
    const int n_img = bi / BPI;
    const int l0    = (bi - n_img * BPI) * BN;
    const int h0    = l0 / WDIM;
    const int w0    = l0 - h0 * WDIM;
    const uint32_t* xp = g_xp + (size_t)n_img * CI_ * HW_;

    // B-gather geometry
    const int n   = tid & 127;
    const int grp = tid >> 7;         // 0..3
    int wc = w0 + n, hh = h0, wp = wc;
    if (wc >= WDIM) { hh = h0 + 1; wp = wc - WDIM; }
    const int base_hw = hh * WDIM + wp;

    // A cp.async geometry
    const int arow = tid >> 2;
    const int aq   = tid & 3;

    float acc[8][4];
#pragma unroll
    for (int i = 0; i < 8; ++i)
#pragma unroll
        for (int j = 0; j < 4; ++j) acc[i][j] = 0.0f;

    uint32_t stash[16];

    const int lm = lid >> 3;
    const int lr = lid & 7;

    auto gatherB = [&](int kblk) {
#pragma unroll
        for (int it = 0; it < 2; ++it) {
            const int oct = grp + it * 4;
            int k  = kblk * KBLK + oct * 8;
            int ci = k / 9;
            int r  = k - ci * 9;
            int kh = r / 3;
            int kw = r - kh * 3;
#pragma unroll
            for (int j = 0; j < 8; ++j) {
                const int hi = hh + kh - 1;
                const int wi = wp + kw - 1;
                uint32_t v = 0;
                if ((unsigned)hi < HDIM && (unsigned)wi < WDIM)
                    v = __ldg(xp + ci * HW_ + base_hw + (kh - 1) * WDIM + (kw - 1));
                stash[it * 8 + j] = v;
                if (++kw == 3) { kw = 0; if (++kh == 3) { kh = 0; ++ci; } }
            }
        }
    };
    auto cpasyncA = [&](int kblk, int buf) {
        const uint32_t dA = sBase + buf * 2 * TILE_B
                          + (uint32_t)(arow * SROW + aq * 32);
        const __nv_bfloat16* sh = &g_wh[arow * KTOT + kblk * KBLK + aq * 16];
        const __nv_bfloat16* sl = &g_wl[arow * KTOT + kblk * KBLK + aq * 16];
        cp16(dA,               sh);
        cp16(dA + 16,          sh + 8);
        cp16(dA + TILE_B,      sl);
        cp16(dA + TILE_B + 16, sl + 8);
        CP_COMMIT();
    };
    auto stsB = [&](int buf) {
        char* tBh = smem + (4 + buf * 2) * TILE_B;
        char* tBl = tBh + TILE_B;
#pragma unroll
        for (int it = 0; it < 2; ++it) {
            const int oct = grp + it * 4;
            const uint32_t* u = &stash[it * 8];
            uint4 ph, pl;
            ph.x = __byte_perm(u[0], u[1], 0x5410);
            ph.y = __byte_perm(u[2], u[3], 0x5410);
            ph.z = __byte_perm(u[4], u[5], 0x5410);
            ph.w = __byte_perm(u[6], u[7], 0x5410);
            pl.x = __byte_perm(u[0], u[1], 0x7632);
            pl.y = __byte_perm(u[2], u[3], 0x7632);
            pl.z = __byte_perm(u[4], u[5], 0x7632);
            pl.w = __byte_perm(u[6], u[7], 0x7632);
            const int off = n * SROW + oct * 16;
            *reinterpret_cast<uint4*>(tBh + off) = ph;
            *reinterpret_cast<uint4*>(tBl + off) = pl;
        }
    };
    auto compute = [&](int buf) {
        const uint32_t sAh = sBase + buf * 2 * TILE_B;
        const uint32_t sAl = sAh + TILE_B;
        const uint32_t sBh = sBase + (4 + buf * 2) * TILE_B;
        const uint32_t sBl = sBh + TILE_B;
#pragma unroll
        for (int ks = 0; ks < 4; ++ks) {
            const int kbyte = ks * 32;
            uint32_t aH[2][4], aL[2][4], bH[4][2], bL[4][2];
#pragma unroll
            for (int mt = 0; mt < 2; ++mt) {
                uint32_t aoff = (uint32_t)((warp_m * 32 + mt * 16 + ((lm & 1) << 3) + lr) * SROW
                                           + kbyte + ((lm >> 1) << 4));
                ldsm_x4(aH[mt], sAh + aoff);
                ldsm_x4(aL[mt], sAl + aoff);
            }
#pragma unroll
            for (int p = 0; p < 2; ++p) {
                uint32_t boff = (uint32_t)((warp_n * 32 + p * 16 + ((lm >> 1) << 3) + lr) * SROW
                                           + kbyte + ((lm & 1) << 4));
                uint32_t rb[4];
                ldsm_x4(rb, sBh + boff);
                bH[2 * p][0] = rb[0]; bH[2 * p][1] = rb[1];
                bH[2 * p + 1][0] = rb[2]; bH[2 * p + 1][1] = rb[3];
                ldsm_x4(rb, sBl + boff);
                bL[2 * p][0] = rb[0]; bL[2 * p][1] = rb[1];
                bL[2 * p + 1][0] = rb[2]; bL[2 * p + 1][1] = rb[3];
            }
#pragma unroll
            for (int mt = 0; mt < 2; ++mt)
#pragma unroll
                for (int nt = 0; nt < 4; ++nt) {
                    float* c = acc[mt * 4 + nt];
                    mma16816(c, aH[mt], bH[nt]);
                    mma16816(c, aH[mt], bL[nt]);
                    mma16816(c, aL[mt], bH[nt]);
                }
        }
    };

    // ---- prologue: stage block 0 into buffers 0 ----
    gatherB(0);
    cpasyncA(0, 0);
    stsB(0);
    CP_WAIT0();
    __syncthreads();

    // ---- main pipeline: ONE sync per block ----
    for (int b = 0; b < NBLKS; ++b) {
        const int cur = b & 1;
        const int nxt = (b + 1) & 1;
        if (b + 1 < NBLKS) {
            gatherB(b + 1);                 // LDGs in flight during compute
            cpasyncA(b + 1, nxt);           // async A into other buffer
        }
        compute(cur);
        if (b + 1 < NBLKS) {
            stsB(nxt);                      // write OTHER B buffer: no hazard,
            CP_WAIT0();                     // no rendezvous needed first
            __syncthreads();                // publish for next iteration
        }
    }

    // ---- epilogue ----
    const int qr = lid >> 2;
    const int qc = lid & 3;
#pragma unroll
    for (int mt = 0; mt < 2; ++mt) {
        const int m0 = warp_m * 32 + mt * 16 + qr;
        const float bv0 = __ldg(bias + m0);
        const float bv1 = __ldg(bias + m0 + 8);
        float* r0 = out + ((size_t)n_img * CO_ + m0) * HW_ + l0;
        float* r1 = r0 + 8 * HW_;
#pragma unroll
        for (int nt = 0; nt < 4; ++nt) {
            const float* c = acc[mt * 4 + nt];
            const int col = warp_n * 32 + nt * 8 + qc * 2;
            *reinterpret_cast<float2*>(r0 + col) = make_float2(c[0] + bv0, c[1] + bv0);
            *reinterpret_cast<float2*>(r1 + col) = make_float2(c[2] + bv1, c[3] + bv1);
        }
    }
}

extern "C" void kernel_launch(void* const* d_in, const int* in_sizes, int n_in,
                              void* d_out, int out_size) {
    const float* x    = (const float*)d_in[0];
    const float* w    = (const float*)d_in[1];
    const float* bias = (const float*)d_in[2];
    float* out        = (float*)d_out;

    cudaFuncSetAttribute(conv_mma_kernel,
                         cudaFuncAttributeMaxDynamicSharedMemorySize, SMEM_TOTAL);

    conv_prep_w<<<(CO_ * KTOT + 255) / 256, 256>>>(w);
    conv_prep_x<<<XELEMS / 4 / 256, 256>>>((const float4*)x);
    conv_mma_kernel<<<NCTAS, NTHR, SMEM_TOTAL>>>(bias, out);
}

// round 15
// speedup vs baseline: 1.5679x; 1.5679x over previous
#include <cuda_runtime.h>
#include <cuda_fp16.h>
#include <cstdint>

// Conv2d 3x3 s1 p1 NCHW fp32 — implicit GEMM on mma.sync fp16 (m16n8k16),
// SINGLE pass: w,x rounded once to fp16, fp32 accumulate.
// Norm rel-err theory (validated on 3-pass: pred 5e-6, meas 4.9e-6): ~4e-4.
// GEMM: M=128 (C_out), N=802816 (spatial), K=576.
// Structure = R8 (best measured): A double-buffered via cp.async,
// B single-buffered with register-stash gather prefetch, 2 syncs/block.

#define CI_   64
#define CO_   128
#define HDIM  224
#define WDIM  224
#define HW_   (HDIM*WDIM)          // 50176
#define KTOT  576
#define KBLK  64
#define NBLKS 9
#define BN    128
#define BPI   (HW_/BN)             // 392
#define NCTAS (16*BPI)             // 6272
#define XELEMS (16*CI_*HW_)        // 51380224
#define NTHR  512

#define SROW  144                  // padded row stride (bytes), 64 fp16 per row
#define TILE_B (128*SROW)          // 18432
// layout: A0 A1 B
#define SMEM_TOTAL (3*TILE_B)      // 55296

__device__ __half   g_wf[CO_*KTOT];
__device__ uint16_t g_xh[XELEMS];   // x rounded to fp16

static __device__ __forceinline__ uint32_t smem_u32(const void* p) {
    uint32_t a;
    asm("{ .reg .u64 t; cvta.to.shared.u64 t, %1; cvt.u32.u64 %0, t; }" : "=r"(a) : "l"(p));
    return a;
}
static __device__ __forceinline__ void ldsm_x4(uint32_t* r, uint32_t addr) {
    asm volatile("ldmatrix.sync.aligned.m8n8.x4.shared.b16 {%0,%1,%2,%3}, [%4];"
        : "=r"(r[0]), "=r"(r[1]), "=r"(r[2]), "=r"(r[3]) : "r"(addr));
}
static __device__ __forceinline__ void mma16816(float* c, const uint32_t* a, const uint32_t* b) {
    asm volatile(
        "mma.sync.aligned.m16n8k16.row.col.f32.f16.f16.f32 "
        "{%0,%1,%2,%3}, {%4,%5,%6,%7}, {%8,%9}, {%0,%1,%2,%3};"
        : "+f"(c[0]), "+f"(c[1]), "+f"(c[2]), "+f"(c[3])
        : "r"(a[0]), "r"(a[1]), "r"(a[2]), "r"(a[3]), "r"(b[0]), "r"(b[1]));
}
static __device__ __forceinline__ void cp16(uint32_t dst, const void* src) {
    asm volatile("cp.async.cg.shared.global [%0], [%1], 16;" :: "r"(dst), "l"(src));
}
#define CP_COMMIT() asm volatile("cp.async.commit_group;" ::: "memory")
#define CP_WAIT0()  asm volatile("cp.async.wait_group 0;" ::: "memory")

// ---------------- prologue kernels ----------------
__global__ void conv_prep_w(const float* __restrict__ w) {
    int i = blockIdx.x * 256 + threadIdx.x;
    if (i < CO_ * KTOT) g_wf[i] = __float2half_rn(w[i]);
}
__global__ void conv_prep_x(const float4* __restrict__ x4) {
    int i = blockIdx.x * 256 + threadIdx.x;     // XELEMS/4 iters
    float4 v = x4[i];
    uint32_t h0 = (uint32_t)__half_as_ushort(__float2half_rn(v.x));
    uint32_t h1 = (uint32_t)__half_as_ushort(__float2half_rn(v.y));
    uint32_t h2 = (uint32_t)__half_as_ushort(__float2half_rn(v.z));
    uint32_t h3 = (uint32_t)__half_as_ushort(__float2half_rn(v.w));
    uint2 p = make_uint2(h0 | (h1 << 16), h2 | (h3 << 16));
    reinterpret_cast<uint2*>(g_xh)[i] = p;
}

// ---------------- main kernel ----------------
__global__ void __launch_bounds__(NTHR)
conv_mma_kernel(const float* __restrict__ bias,
                float* __restrict__ out) {
    extern __shared__ char smem[];
    char* tB = smem + 2 * TILE_B;
    const uint32_t sBase = smem_u32(smem);
    const uint32_t sB = sBase + 2 * TILE_B;

    const int tid = threadIdx.x;
    const int wid = tid >> 5;
    const int lid = tid & 31;
    const int warp_m = wid & 3;       // 4 warps over M, 32 rows each
    const int warp_n = wid >> 2;      // 4 warps over N, 32 cols each

    const int bi    = blockIdx.x;
    const int n_img = bi / BPI;
    const int l0    = (bi - n_img * BPI) * BN;
    const int h0    = l0 / WDIM;
    const int w0    = l0 - h0 * WDIM;
    const uint16_t* xh = g_xh + (size_t)n_img * CI_ * HW_;

    // B-gather geometry: thread handles (n, 16 consecutive k)
    const int n   = tid & 127;
    const int grp = tid >> 7;         // 0..3 -> k range grp*16..grp*16+15
    int wc = w0 + n, hh = h0, wp = wc;
    if (wc >= WDIM) { hh = h0 + 1; wp = wc - WDIM; }
    const int base_hw = hh * WDIM + wp;

    // A cp.async geometry: row = tid>>2, 32B quarter = tid&3
    const int arow = tid >> 2;
    const int aq   = tid & 3;

    float acc[8][4];
#pragma unroll
    for (int i = 0; i < 8; ++i)
#pragma unroll
        for (int j = 0; j < 4; ++j) acc[i][j] = 0.0f;

    uint32_t stash[16];               // zero-extended fp16 gathers

    const int lm = lid >> 3;
    const int lr = lid & 7;

    auto gatherB = [&](int kblk) {
        int k  = kblk * KBLK + grp * 16;
        int ci = k / 9;
        int r  = k - ci * 9;
        int kh = r / 3;
        int kw = r - kh * 3;
#pragma unroll
        for (int j = 0; j < 16; ++j) {
            const int hi = hh + kh - 1;
            const int wi = wp + kw - 1;
            uint32_t v = 0;
            if ((unsigned)hi < HDIM && (unsigned)wi < WDIM)
                v = (uint32_t)__ldg(xh + ci * HW_ + base_hw + (kh - 1) * WDIM + (kw - 1));
            stash[j] = v;
            if (++kw == 3) { kw = 0; if (++kh == 3) { kh = 0; ++ci; } }
        }
    };
    auto cpasyncA = [&](int kblk, int buf) {
        const uint32_t dA = sBase + buf * TILE_B
                          + (uint32_t)(arow * SROW + aq * 32);
        const __half* s = &g_wf[arow * KTOT + kblk * KBLK + aq * 16];
        cp16(dA,      s);
        cp16(dA + 16, s + 8);
        CP_COMMIT();
    };
    auto stsB = [&]() {
        uint4 p0, p1;
        p0.x = stash[0]  | (stash[1]  << 16);
        p0.y = stash[2]  | (stash[3]  << 16);
        p0.z = stash[4]  | (stash[5]  << 16);
        p0.w = stash[6]  | (stash[7]  << 16);
        p1.x = stash[8]  | (stash[9]  << 16);
        p1.y = stash[10] | (stash[11] << 16);
        p1.z = stash[12] | (stash[13] << 16);
        p1.w = stash[14] | (stash[15] << 16);
        const int off = n * SROW + grp * 32;
        *reinterpret_cast<uint4*>(tB + off)      = p0;
        *reinterpret_cast<uint4*>(tB + off + 16) = p1;
    };
    auto compute = [&](int buf) {
        const uint32_t sA = sBase + buf * TILE_B;
#pragma unroll
        for (int ks = 0; ks < 4; ++ks) {
            const int kbyte = ks * 32;
            uint32_t aF[2][4], bF[4][2];
#pragma unroll
            for (int mt = 0; mt < 2; ++mt) {
                uint32_t aoff = (uint32_t)((warp_m * 32 + mt * 16 + ((lm & 1) << 3) + lr) * SROW
                                           + kbyte + ((lm >> 1) << 4));
                ldsm_x4(aF[mt], sA + aoff);
            }
#pragma unroll
            for (int p = 0; p < 2; ++p) {
                uint32_t boff = (uint32_t)((warp_n * 32 + p * 16 + ((lm >> 1) << 3) + lr) * SROW
                                           + kbyte + ((lm & 1) << 4));
                uint32_t rb[4];
                ldsm_x4(rb, sB + boff);
                bF[2 * p][0] = rb[0]; bF[2 * p][1] = rb[1];
                bF[2 * p + 1][0] = rb[2]; bF[2 * p + 1][1] = rb[3];
            }
#pragma unroll
            for (int mt = 0; mt < 2; ++mt)
#pragma unroll
                for (int nt = 0; nt < 4; ++nt)
                    mma16816(acc[mt * 4 + nt], aF[mt], bF[nt]);
        }
    };

    // ---- prologue: stage block 0 ----
    gatherB(0);
    cpasyncA(0, 0);
    stsB();
    CP_WAIT0();
    __syncthreads();

    // ---- main pipeline (R8 structure) ----
    for (int b = 0; b < NBLKS; ++b) {
        if (b + 1 < NBLKS) {
            gatherB(b + 1);                 // LDGs in flight during compute
            cpasyncA(b + 1, (b + 1) & 1);   // async A into other buffer
        }
        compute(b & 1);
        __syncthreads();
        if (b + 1 < NBLKS) {
            stsB();                         // consume stash (LDGs landed)
            CP_WAIT0();
            __syncthreads();
        }
    }

    // ---- epilogue ----
    const int qr = lid >> 2;
    const int qc = lid & 3;
#pragma unroll
    for (int mt = 0; mt < 2; ++mt) {
        const int m0 = warp_m * 32 + mt * 16 + qr;
        const float bv0 = __ldg(bias + m0);
        const float bv1 = __ldg(bias + m0 + 8);
        float* r0 = out + ((size_t)n_img * CO_ + m0) * HW_ + l0;
        float* r1 = r0 + 8 * HW_;
#pragma unroll
        for (int nt = 0; nt < 4; ++nt) {
            const float* c = acc[mt * 4 + nt];
            const int col = warp_n * 32 + nt * 8 + qc * 2;
            *reinterpret_cast<float2*>(r0 + col) = make_float2(c[0] + bv0, c[1] + bv0);
            *reinterpret_cast<float2*>(r1 + col) = make_float2(c[2] + bv1, c[3] + bv1);
        }
    }
}

extern "C" void kernel_launch(void* const* d_in, const int* in_sizes, int n_in,
                              void* d_out, int out_size) {
    const float* x    = (const float*)d_in[0];
    const float* w    = (const float*)d_in[1];
    const float* bias = (const float*)d_in[2];
    float* out        = (float*)d_out;

    cudaFuncSetAttribute(conv_mma_kernel,
                         cudaFuncAttributeMaxDynamicSharedMemorySize, SMEM_TOTAL);

    conv_prep_w<<<(CO_ * KTOT + 255) / 256, 256>>>(w);
    conv_prep_x<<<XELEMS / 4 / 256, 256>>>((const float4*)x);
    conv_mma_kernel<<<NCTAS, NTHR, SMEM_TOTAL>>>(bias, out);
}

// round 16
// speedup vs baseline: 1.6151x; 1.0302x over previous
#include <cuda_runtime.h>
#include <cuda_fp16.h>
#include <cstdint>

// Conv2d 3x3 s1 p1 NCHW fp32 — implicit GEMM on mma.sync fp16 (m16n8k16),
// single pass (w,x rounded once to fp16), fp32 accumulate. rel_err ~3e-4.
// GEMM: M=128 (C_out), N=802816 (spatial), K=576.
// R16: BN=256 — two N-halves share k-loop/A-tiles/barriers to amortize the
// measured ~3.7k cyc/block fixed overhead. Half the B gathers are register-
// stash prefetched; the other half gathered in the build phase.

#define CI_   64
#define CO_   128
#define HDIM  224
#define WDIM  224
#define HW_   (HDIM*WDIM)          // 50176
#define KTOT  576
#define KBLK  64
#define NBLKS 9
#define BN    256
#define BPI   (HW_/BN)             // 196
#define NCTAS (16*BPI)             // 3136
#define XELEMS (16*CI_*HW_)        // 51380224
#define NTHR  512

#define SROW  144                  // padded row stride (bytes), 64 fp16 per row
#define TILE_A (128*SROW)          // 18432
#define TILE_BB (256*SROW)         // 36864
// layout: A0 A1 B
#define SMEM_TOTAL (2*TILE_A + TILE_BB)   // 73728

__device__ __half   g_wf[CO_*KTOT];
__device__ uint16_t g_xh[XELEMS];   // x rounded to fp16

static __device__ __forceinline__ uint32_t smem_u32(const void* p) {
    uint32_t a;
    asm("{ .reg .u64 t; cvta.to.shared.u64 t, %1; cvt.u32.u64 %0, t; }" : "=r"(a) : "l"(p));
    return a;
}
static __device__ __forceinline__ void ldsm_x4(uint32_t* r, uint32_t addr) {
    asm volatile("ldmatrix.sync.aligned.m8n8.x4.shared.b16 {%0,%1,%2,%3}, [%4];"
        : "=r"(r[0]), "=r"(r[1]), "=r"(r[2]), "=r"(r[3]) : "r"(addr));
}
static __device__ __forceinline__ void mma16816(float* c, const uint32_t* a, const uint32_t* b) {
    asm volatile(
        "mma.sync.aligned.m16n8k16.row.col.f32.f16.f16.f32 "
        "{%0,%1,%2,%3}, {%4,%5,%6,%7}, {%8,%9}, {%0,%1,%2,%3};"
        : "+f"(c[0]), "+f"(c[1]), "+f"(c[2]), "+f"(c[3])
        : "r"(a[0]), "r"(a[1]), "r"(a[2]), "r"(a[3]), "r"(b[0]), "r"(b[1]));
}
static __device__ __forceinline__ void cp16(uint32_t dst, const void* src) {
    asm volatile("cp.async.cg.shared.global [%0], [%1], 16;" :: "r"(dst), "l"(src));
}
#define CP_COMMIT() asm volatile("cp.async.commit_group;" ::: "memory")
#define CP_WAIT0()  asm volatile("cp.async.wait_group 0;" ::: "memory")

// ---------------- prologue kernels ----------------
__global__ void conv_prep_w(const float* __restrict__ w) {
    int i = blockIdx.x * 256 + threadIdx.x;
    if (i < CO_ * KTOT) g_wf[i] = __float2half_rn(w[i]);
}
__global__ void conv_prep_x(const float4* __restrict__ x4) {
    int i = blockIdx.x * 256 + threadIdx.x;
    float4 v = x4[i];
    uint32_t h0 = (uint32_t)__half_as_ushort(__float2half_rn(v.x));
    uint32_t h1 = (uint32_t)__half_as_ushort(__float2half_rn(v.y));
    uint32_t h2 = (uint32_t)__half_as_ushort(__float2half_rn(v.z));
    uint32_t h3 = (uint32_t)__half_as_ushort(__float2half_rn(v.w));
    reinterpret_cast<uint2*>(g_xh)[i] = make_uint2(h0 | (h1 << 16), h2 | (h3 << 16));
}

// ---------------- main kernel ----------------
__global__ void __launch_bounds__(NTHR)
conv_mma_kernel(const float* __restrict__ bias,
                float* __restrict__ out) {
    extern __shared__ char smem[];
    char* tB = smem + 2 * TILE_A;
    const uint32_t sBase = smem_u32(smem);
    const uint32_t sB = sBase + 2 * TILE_A;

    const int tid = threadIdx.x;
    const int wid = tid >> 5;
    const int lid = tid & 31;
    const int warp_m = wid & 3;       // 4 warps over M, 32 rows each
    const int warp_n = wid >> 2;      // 4 warps over N, 64 cols each

    const int bi    = blockIdx.x;
    const int n_img = bi / BPI;
    const int l0    = (bi - n_img * BPI) * BN;
    const int h0    = l0 / WDIM;
    const int w0    = l0 - h0 * WDIM;
    const uint16_t* xh = g_xh + (size_t)n_img * CI_ * HW_;

    // B-gather geometry: thread -> (n, 32 k split in two 16-halves)
    const int n   = tid & 255;
    const int grp = tid >> 8;         // 0..1 -> k base grp*32
    const int wc  = w0 + n;
    const int hh  = h0 + wc / WDIM;   // up to h0+2
    const int wp  = wc - (hh - h0) * WDIM;

    // A cp.async geometry
    const int arow = tid >> 2;
    const int aq   = tid & 3;

    float acc[16][4];
#pragma unroll
    for (int i = 0; i < 16; ++i)
#pragma unroll
        for (int j = 0; j < 4; ++j) acc[i][j] = 0.0f;

    uint32_t stash[16];

    const int lm = lid >> 3;
    const int lr = lid & 7;

    // gather 16 k values starting at relative k (krel) into dst registers
    auto gather16 = [&](int kblk, int krel, uint32_t* dst) {
        int k  = kblk * KBLK + krel;
        int ci = k / 9;
        int r  = k - ci * 9;
        int kh = r / 3;
        int kw = r - kh * 3;
#pragma unroll
        for (int j = 0; j < 16; ++j) {
            const int hi = hh + kh - 1;
            const int wi = wp + kw - 1;
            uint32_t v = 0;
            if ((unsigned)hi < HDIM && (unsigned)wi < WDIM)
                v = (uint32_t)__ldg(xh + ci * HW_ + hi * WDIM + wi);
            dst[j] = v;
            if (++kw == 3) { kw = 0; if (++kh == 3) { kh = 0; ++ci; } }
        }
    };
    auto pack_sts = [&](const uint32_t* u, int byte_off) {
        uint4 p0, p1;
        p0.x = u[0]  | (u[1]  << 16);
        p0.y = u[2]  | (u[3]  << 16);
        p0.z = u[4]  | (u[5]  << 16);
        p0.w = u[6]  | (u[7]  << 16);
        p1.x = u[8]  | (u[9]  << 16);
        p1.y = u[10] | (u[11] << 16);
        p1.z = u[12] | (u[13] << 16);
        p1.w = u[14] | (u[15] << 16);
        *reinterpret_cast<uint4*>(tB + byte_off)      = p0;
        *reinterpret_cast<uint4*>(tB + byte_off + 16) = p1;
    };
    auto cpasyncA = [&](int kblk, int buf) {
        const uint32_t dA = sBase + buf * TILE_A
                          + (uint32_t)(arow * SROW + aq * 32);
        const __half* s = &g_wf[arow * KTOT + kblk * KBLK + aq * 16];
        cp16(dA,      s);
        cp16(dA + 16, s + 8);
        CP_COMMIT();
    };
    // build: stash half (k rel grp*32..+15) + direct half (grp*32+16..+31)
    auto buildB = [&](int kblk) {
        pack_sts(stash, n * SROW + grp * 64);
        uint32_t tmp[16];
        gather16(kblk, grp * 32 + 16, tmp);
        pack_sts(tmp, n * SROW + grp * 64 + 32);
    };
    auto compute = [&](int buf) {
        const uint32_t sA = sBase + buf * TILE_A;
#pragma unroll
        for (int ks = 0; ks < 4; ++ks) {
            const int kbyte = ks * 32;
            uint32_t aF[2][4];
#pragma unroll
            for (int mt = 0; mt < 2; ++mt) {
                uint32_t aoff = (uint32_t)((warp_m * 32 + mt * 16 + ((lm & 1) << 3) + lr) * SROW
                                           + kbyte + ((lm >> 1) << 4));
                ldsm_x4(aF[mt], sA + aoff);
            }
#pragma unroll
            for (int p = 0; p < 4; ++p) {
                uint32_t boff = (uint32_t)((warp_n * 64 + p * 16 + ((lm >> 1) << 3) + lr) * SROW
                                           + kbyte + ((lm & 1) << 4));
                uint32_t rb[4];
                ldsm_x4(rb, sB + boff);
#pragma unroll
                for (int mt = 0; mt < 2; ++mt) {
                    mma16816(acc[mt * 8 + 2 * p],     aF[mt], rb);
                    mma16816(acc[mt * 8 + 2 * p + 1], aF[mt], rb + 2);
                }
            }
        }
    };

    // ---- prologue: stage block 0 ----
    gather16(0, grp * 32, stash);
    cpasyncA(0, 0);
    buildB(0);
    CP_WAIT0();
    __syncthreads();

    // ---- main pipeline ----
    for (int b = 0; b < NBLKS; ++b) {
        if (b + 1 < NBLKS) {
            gather16(b + 1, grp * 32, stash);   // prefetch half of next B
            cpasyncA(b + 1, (b + 1) & 1);       // async A into other buffer
        }
        compute(b & 1);
        __syncthreads();                        // B consumed
        if (b + 1 < NBLKS) {
            buildB(b + 1);                      // stash STS + direct half
            CP_WAIT0();
            __syncthreads();                    // publish
        }
    }

    // ---- epilogue ----
    const int qr = lid >> 2;
    const int qc = lid & 3;
#pragma unroll
    for (int mt = 0; mt < 2; ++mt) {
        const int m0 = warp_m * 32 + mt * 16 + qr;
        const float bv0 = __ldg(bias + m0);
        const float bv1 = __ldg(bias + m0 + 8);
        float* r0 = out + ((size_t)n_img * CO_ + m0) * HW_ + l0;
        float* r1 = r0 + 8 * HW_;
#pragma unroll
        for (int nt = 0; nt < 8; ++nt) {
            const float* c = acc[mt * 8 + nt];
            const int col = warp_n * 64 + nt * 8 + qc * 2;
            *reinterpret_cast<float2*>(r0 + col) = make_float2(c[0] + bv0, c[1] + bv0);
            *reinterpret_cast<float2*>(r1 + col) = make_float2(c[2] + bv1, c[3] + bv1);
        }
    }
}

extern "C" void kernel_launch(void* const* d_in, const int* in_sizes, int n_in,
                              void* d_out, int out_size) {
    const float* x    = (const float*)d_in[0];
    const float* w    = (const float*)d_in[1];
    const float* bias = (const float*)d_in[2];
    float* out        = (float*)d_out;

    cudaFuncSetAttribute(conv_mma_kernel,
                         cudaFuncAttributeMaxDynamicSharedMemorySize, SMEM_TOTAL);

    conv_prep_w<<<(CO_ * KTOT + 255) / 256, 256>>>(w);
    conv_prep_x<<<XELEMS / 4 / 256, 256>>>((const float4*)x);
    conv_mma_kernel<<<NCTAS, NTHR, SMEM_TOTAL>>>(bias, out);
}